// round 8
// baseline (speedup 1.0000x reference)
#include <cuda_runtime.h>
#include <cuda_bf16.h>
#include <math.h>

// Problem constants (match reference)
#define BATCH     8
#define NPI       1000      // proposals per image
#define NC        81        // classes incl. background
#define CF        80        // foreground classes
#define BN        (BATCH*NPI)
#define DETS      100
#define SCORE_TH  0.05f
#define NMS_TH    0.5f
#define IMG_W1    1332.0f   // IMG_W - 1
#define IMG_H1    799.0f    // IMG_H - 1
#define DW_CLIP_F 4.135166556742356f   // log(1000/16)

#define CAND_CAP  (CF * DETS)   // 8000: per-class cap 100 makes this exact

typedef unsigned long long u64;
typedef unsigned int u32;

// Scratch (device globals; no allocation allowed)
__device__ float g_scores[BATCH * CF * NPI];        // [b][c0][n]   (NMS reads coalesced)
__device__ float g_boxes [BN * CF * 4];             // [n_global][c0][4] (coalesced writes)
__device__ u64   g_cand[BATCH * CAND_CAP];          // per-image kept entries
__device__ int   g_cnt[BATCH];

// ===========================================================================
// Warp-register bitonic machinery: 128 u64 keys per warp, 4 per lane,
// element index e = r*32 + lane. Descending order. No barriers, no smem.
// ===========================================================================
__device__ __forceinline__ void cedir(u64 &a, u64 &b, bool maxlow) {
    u64 mx = a > b ? a : b;
    u64 mn = a > b ? b : a;
    a = maxlow ? mx : mn;
    b = maxlow ? mn : mx;
}

__device__ __forceinline__ void shflpass(u64 v[4], int lane, int k, int j) {
    #pragma unroll
    for (int r = 0; r < 4; r++) {
        u64 o = __shfl_xor_sync(0xFFFFFFFFu, v[r], j);
        int e = (r << 5) | lane;
        bool keepmax = (((e & k) == 0) == ((lane & j) == 0));
        bool gt = v[r] > o;
        u64 mx = gt ? v[r] : o;
        u64 mn = gt ? o : v[r];
        v[r] = keepmax ? mx : mn;
    }
}

__device__ __forceinline__ void warp_sort128_desc(u64 v[4], int lane) {
    #pragma unroll
    for (int k = 2; k <= 32; k <<= 1) {
        #pragma unroll
        for (int j = k >> 1; j >= 1; j >>= 1) shflpass(v, lane, k, j);
    }
    // k = 64: j=32 is a register exchange (pairs (v0,v1) desc, (v2,v3) asc)
    cedir(v[0], v[1], true);
    cedir(v[2], v[3], false);
    #pragma unroll
    for (int j = 16; j >= 1; j >>= 1) shflpass(v, lane, 64, j);
    // k = 128: j=64, j=32 register exchanges, all-descending
    cedir(v[0], v[2], true); cedir(v[1], v[3], true);
    cedir(v[0], v[1], true); cedir(v[2], v[3], true);
    #pragma unroll
    for (int j = 16; j >= 1; j >>= 1) shflpass(v, lane, 128, j);
}

// Clean a bitonic 128-sequence into descending order.
__device__ __forceinline__ void warp_merge128_desc(u64 v[4], int lane) {
    cedir(v[0], v[2], true); cedir(v[1], v[3], true);
    cedir(v[0], v[1], true); cedir(v[2], v[3], true);
    #pragma unroll
    for (int j = 16; j >= 1; j >>= 1) {
        #pragma unroll
        for (int r = 0; r < 4; r++) {
            u64 o = __shfl_xor_sync(0xFFFFFFFFu, v[r], j);
            bool keepmax = ((lane & j) == 0);
            bool gt = v[r] > o;
            u64 mx = gt ? v[r] : o;
            u64 mn = gt ? o : v[r];
            v[r] = keepmax ? mx : mn;
        }
    }
}

// ===========================================================================
// One WARP per proposal: shfl softmax over 81 classes, decode+clip 80 boxes.
// Boxes stored [n_global][c0][4] -> coalesced float4 stores.
// ===========================================================================
__global__ void softmax_decode_kernel(const float* __restrict__ logits,
                                      const float* __restrict__ reg,
                                      const float* __restrict__ props) {
    if (blockIdx.x == 0 && threadIdx.x < BATCH) g_cnt[threadIdx.x] = 0;

    int n    = (blockIdx.x * blockDim.x + threadIdx.x) >> 5;
    int lane = threadIdx.x & 31;
    if (n >= BN) return;

    const float* lrow = logits + n * NC;
    float l0 = lrow[lane];
    float l1 = lrow[lane + 32];
    float l2 = (lane + 64 < NC) ? lrow[lane + 64] : -INFINITY;

    float mx = fmaxf(l0, fmaxf(l1, l2));
    #pragma unroll
    for (int o = 16; o > 0; o >>= 1) mx = fmaxf(mx, __shfl_xor_sync(0xFFFFFFFFu, mx, o));

    float e0 = expf(l0 - mx);
    float e1 = expf(l1 - mx);
    float e2 = (lane + 64 < NC) ? expf(l2 - mx) : 0.0f;
    float sm = e0 + e1 + e2;
    #pragma unroll
    for (int o = 16; o > 0; o >>= 1) sm += __shfl_xor_sync(0xFFFFFFFFu, sm, o);
    float inv = 1.0f / sm;

    float4 p = *(const float4*)(props + n * 4);
    float w  = p.z - p.x + 1.0f;
    float h  = p.w - p.y + 1.0f;
    float cx = p.x + 0.5f * w;
    float cy = p.y + 0.5f * h;

    int b  = n / NPI;
    int nl = n - b * NPI;

    #pragma unroll
    for (int s = 0; s < 3; s++) {
        int c = lane + 32 * s;
        if (c >= 1 && c < NC) {
            int c0 = c - 1;
            float e = (s == 0) ? e0 : (s == 1) ? e1 : e2;
            g_scores[(b * CF + c0) * NPI + nl] = e * inv;

            float4 r = *(const float4*)(reg + n * (NC * 4) + c * 4);
            float dx = r.x * 0.1f;
            float dy = r.y * 0.1f;
            float dw = fminf(r.z * 0.2f, DW_CLIP_F);
            float dh = fminf(r.w * 0.2f, DW_CLIP_F);

            float pcx = dx * w + cx;
            float pcy = dy * h + cy;
            float pw  = expf(dw) * w;
            float ph  = expf(dh) * h;

            float bx0 = fminf(fmaxf(pcx - 0.5f * pw, 0.0f), IMG_W1);
            float by0 = fminf(fmaxf(pcy - 0.5f * ph, 0.0f), IMG_H1);
            float bx1 = fminf(fmaxf(pcx + 0.5f * pw - 1.0f, 0.0f), IMG_W1);
            float by1 = fminf(fmaxf(pcy + 0.5f * ph - 1.0f, 0.0f), IMG_H1);

            // coalesced: consecutive c0 across lanes
            *(float4*)(g_boxes + ((size_t)n * CF + c0) * 4) =
                make_float4(bx0, by0, bx1, by1);
        }
    }
}

// ===========================================================================
// One block (128 thr) per (image,class): compact, warp-register sort,
// pairwise-suppression bitmask, single-thread barrier-free greedy scan.
// Dynamic smem layout:
//   [0,8192)       u64   skey[1024]
//   [8192,24576)   float4 sbox[1024]
//   [24576,28672)  float sarea[1024]
//   [28672,36864)  u32   smask[256*8]   (or uchar ssup[1024] overlay, fallback)
//   [36864,37696)  u64   skept[104]
// ===========================================================================
#define NMS_SMEM 37696

__global__ void nms_kernel() {
    extern __shared__ char nsm[];
    u64*    skey  = (u64*)nsm;
    float4* sbox  = (float4*)(nsm + 8192);
    float*  sarea = (float*)(nsm + 24576);
    u32*    smask = (u32*)(nsm + 28672);
    unsigned char* ssup = (unsigned char*)(nsm + 28672);
    u64*    skept = (u64*)(nsm + 36864);

    __shared__ int s_cnt, s_kcnt, s_base;

    int task = blockIdx.x;       // 0..639
    int b  = task / CF;
    int c0 = task - b * CF;
    int tid  = threadIdx.x;      // 0..127
    int lane = tid & 31;
    int wrp  = tid >> 5;

    if (tid == 0) s_cnt = 0;
    __syncthreads();

    // --- compact valid scores ---
    const float* sc_base = g_scores + (b * CF + c0) * NPI;
    for (int i = tid; i < NPI; i += 128) {
        float s = sc_base[i];
        if (s > SCORE_TH) {
            int p = atomicAdd(&s_cnt, 1);
            skey[p] = ((u64)__float_as_uint(s) << 32) | (u64)(0xFFFFFFFFu - (u32)i);
        }
    }
    __syncthreads();
    int m = s_cnt;
    if (m == 0) return;

    // --- sort descending (score, then lower proposal index) ---
    if (m <= 128) {
        if (wrp == 0) {
            u64 v[4];
            #pragma unroll
            for (int r = 0; r < 4; r++) {
                int e = r * 32 + lane;
                v[r] = (e < m) ? skey[e] : 0ull;
            }
            warp_sort128_desc(v, lane);
            #pragma unroll
            for (int r = 0; r < 4; r++) skey[r * 32 + lane] = v[r];
        }
        __syncthreads();
    } else {
        int L = 128;
        while (L < m) L <<= 1;
        for (int i = m + tid; i < L; i += 128) skey[i] = 0ull;
        __syncthreads();
        for (int k = 2; k <= L; k <<= 1) {
            for (int j = k >> 1; j > 0; j >>= 1) {
                for (int i = tid; i < L; i += 128) {
                    int ixj = i ^ j;
                    if (ixj > i) {
                        u64 a = skey[i], c = skey[ixj];
                        if (((i & k) == 0) ? (a < c) : (a > c)) {
                            skey[i] = c; skey[ixj] = a;
                        }
                    }
                }
                __syncthreads();
            }
        }
    }

    // --- gather boxes in sorted order ---
    for (int i = tid; i < m; i += 128) {
        u32 n = 0xFFFFFFFFu - (u32)(skey[i] & 0xFFFFFFFFull);
        int ng = b * NPI + (int)n;
        float4 bx = *(const float4*)(g_boxes + ((size_t)ng * CF + c0) * 4);
        sbox[i] = bx;
        sarea[i] = (bx.z - bx.x) * (bx.w - bx.y);   // torchvision IoU (no +1)
    }
    __syncthreads();

    u64 keysub = (u64)((u32)c0 * NPI);   // skey -> image-flat key conversion

    if (m <= 256) {
        // --- pairwise suppression bit-matrix (stride 8 u32 words per row) ---
        for (int idx = tid; idx < m * 8; idx += 128) smask[idx] = 0;
        __syncthreads();
        for (int idx = tid; idx < m * m; idx += 128) {
            int i = idx / m;
            int j = idx - i * m;
            if (j > i) {
                float4 bi = sbox[i], bj = sbox[j];
                float lx = fmaxf(bi.x, bj.x);
                float ly = fmaxf(bi.y, bj.y);
                float rx = fminf(bi.z, bj.z);
                float ry = fminf(bi.w, bj.w);
                float iw = fmaxf(rx - lx, 0.0f);
                float ih = fmaxf(ry - ly, 0.0f);
                float inter = iw * ih;
                float iou = inter / (sarea[i] + sarea[j] - inter + 1e-9f);
                if (iou > NMS_TH)
                    atomicOr(&smask[i * 8 + (j >> 5)], 1u << (j & 31));
            }
        }
        __syncthreads();

        // --- barrier-free greedy scan (single thread, pure bit ops) ---
        if (tid == 0) {
            u32 rem[8] = {0,0,0,0,0,0,0,0};
            int kc = 0;
            for (int i = 0; i < m; i++) {
                if (!((rem[i >> 5] >> (i & 31)) & 1u)) {
                    skept[kc++] = skey[i] - keysub;
                    if (kc == DETS) break;
                    #pragma unroll
                    for (int w2 = 0; w2 < 8; w2++) rem[w2] |= smask[i * 8 + w2];
                }
            }
            s_kcnt = kc;
            s_base = atomicAdd(&g_cnt[b], kc);
        }
        __syncthreads();
        if (tid < s_kcnt) g_cand[b * CAND_CAP + s_base + tid] = skept[tid];
    } else {
        // --- fallback: barrier greedy (m > 256; never hit on this data) ---
        for (int i = tid; i < m; i += 128) ssup[i] = 0;
        if (tid == 0) s_kcnt = 0;
        __syncthreads();
        for (int i = 0; i < m; i++) {
            if (!ssup[i]) {
                if (tid == 0 && s_kcnt < DETS) {
                    skept[s_kcnt++] = skey[i] - keysub;
                }
                float4 bi = sbox[i];
                float ai = sarea[i];
                for (int j = i + 1 + tid; j < m; j += 128) {
                    if (!ssup[j]) {
                        float4 bj = sbox[j];
                        float lx = fmaxf(bi.x, bj.x);
                        float ly = fmaxf(bi.y, bj.y);
                        float rx = fminf(bi.z, bj.z);
                        float ry = fminf(bi.w, bj.w);
                        float iw = fmaxf(rx - lx, 0.0f);
                        float ih = fmaxf(ry - ly, 0.0f);
                        float inter = iw * ih;
                        float iou = inter / (ai + sarea[j] - inter + 1e-9f);
                        if (iou > NMS_TH) ssup[j] = 1;
                    }
                }
            }
            __syncthreads();
        }
        if (tid == 0) s_base = atomicAdd(&g_cnt[b], s_kcnt);
        __syncthreads();
        if (tid < s_kcnt) g_cand[b * CAND_CAP + s_base + tid] = skept[tid];
    }
}

// ===========================================================================
// One block (1024 thr = 32 warps) per image. Warp-register bitonic top-k:
// each warp reduces its 256-chunk to a sorted top-128, then 5 tree merge
// rounds (one barrier each). Warp 0 emits the top-100.
// smem: bufA 32*128 u64 (32KB) + bufB 16*128 u64 (16KB) = 48KB dynamic.
// ===========================================================================
#define TOPK_SMEM (48 * 1024)

__global__ void topk_kernel(float* __restrict__ out, int out_size) {
    extern __shared__ u64 tsm[];
    u64* A  = tsm;            // 32 lists of 128
    u64* Bf = tsm + 32 * 128; // 16 lists of 128

    int b    = blockIdx.x;
    int tid  = threadIdx.x;
    int lane = tid & 31;
    int w    = tid >> 5;
    int M    = g_cnt[b];
    if (M > CAND_CAP) M = CAND_CAP;
    const u64* cand = g_cand + b * CAND_CAP;

    // per-warp: load 256, sort two 128s, keep top-128
    u64 v[4], u[4];
    int base = w * 256;
    #pragma unroll
    for (int r = 0; r < 4; r++) {
        int e = base + r * 32 + lane;
        v[r] = (e < M) ? cand[e] : 0ull;
        int e2 = e + 128;
        u[r] = (e2 < M) ? cand[e2] : 0ull;
    }
    warp_sort128_desc(v, lane);
    warp_sort128_desc(u, lane);
    {   // top-128 of the two sorted lists: v[e] = max(v[e], u[127-e])
        u64 o0 = __shfl_xor_sync(0xFFFFFFFFu, u[3], 31);
        u64 o1 = __shfl_xor_sync(0xFFFFFFFFu, u[2], 31);
        u64 o2 = __shfl_xor_sync(0xFFFFFFFFu, u[1], 31);
        u64 o3 = __shfl_xor_sync(0xFFFFFFFFu, u[0], 31);
        v[0] = v[0] > o0 ? v[0] : o0;
        v[1] = v[1] > o1 ? v[1] : o1;
        v[2] = v[2] > o2 ? v[2] : o2;
        v[3] = v[3] > o3 ? v[3] : o3;
        warp_merge128_desc(v, lane);
    }
    #pragma unroll
    for (int r = 0; r < 4; r++) A[w * 128 + r * 32 + lane] = v[r];
    __syncthreads();

    // tree merge rounds: 32 -> 16 -> 8 -> 4 -> 2 -> 1 lists
    #pragma unroll
    for (int round = 0; round < 5; round++) {
        int nl = 16 >> round;                       // active warps this round
        const u64* src = (round & 1) ? Bf : A;
        u64*       dst = (round & 1) ? A  : Bf;
        if (w < nl) {
            const u64* pa = src + (2 * w) * 128;
            const u64* pb = src + (2 * w + 1) * 128;
            #pragma unroll
            for (int r = 0; r < 4; r++) {
                int e = r * 32 + lane;
                u64 a  = pa[e];
                u64 bb = pb[127 - e];
                v[r] = a > bb ? a : bb;
            }
            warp_merge128_desc(v, lane);
            if (nl > 1) {
                #pragma unroll
                for (int r = 0; r < 4; r++) dst[w * 128 + r * 32 + lane] = v[r];
            }
        }
        __syncthreads();
    }

    // warp 0 holds the final sorted 128 in v -> emit top 100
    bool write_labels = (out_size >= BATCH * DETS * 5 + BATCH * DETS);
    if (w == 0) {
        #pragma unroll
        for (int r = 0; r < 4; r++) {
            int e = r * 32 + lane;
            if (e < DETS) {
                u64 bk = v[r];
                float* drow = out + (b * DETS + e) * 5;
                if (bk == 0) {
                    drow[0] = 0.0f; drow[1] = 0.0f; drow[2] = 0.0f;
                    drow[3] = 0.0f; drow[4] = 0.0f;
                    if (write_labels)
                        out[BATCH * DETS * 5 + b * DETS + e] = -1.0f;
                } else {
                    float sc = __uint_as_float((u32)(bk >> 32));
                    u32 flat = 0xFFFFFFFFu - (u32)(bk & 0xFFFFFFFFull);
                    int c0 = (int)(flat / NPI);
                    int n  = (int)(flat - (u32)c0 * NPI);
                    int ng = b * NPI + n;
                    const float* bx = g_boxes + ((size_t)ng * CF + c0) * 4;
                    drow[0] = bx[0]; drow[1] = bx[1];
                    drow[2] = bx[2]; drow[3] = bx[3];
                    drow[4] = sc;
                    if (write_labels)
                        out[BATCH * DETS * 5 + b * DETS + e] = (float)(c0 + 1);
                }
            }
        }
    }
}

// ---------------------------------------------------------------------------
extern "C" void kernel_launch(void* const* d_in, const int* in_sizes, int n_in,
                              void* d_out, int out_size) {
    const float* class_logits   = (const float*)d_in[0];  // [8000, 81]
    const float* box_regression = (const float*)d_in[1];  // [8000, 324]
    const float* proposals      = (const float*)d_in[2];  // [8000, 4]
    // d_in[3] = features (unused)

    float* out = (float*)d_out;

    cudaFuncSetAttribute(topk_kernel,
                         cudaFuncAttributeMaxDynamicSharedMemorySize, TOPK_SMEM);
    cudaFuncSetAttribute(nms_kernel,
                         cudaFuncAttributeMaxDynamicSharedMemorySize, NMS_SMEM);

    softmax_decode_kernel<<<BN / 8, 256>>>(class_logits, box_regression, proposals);
    nms_kernel<<<BATCH * CF, 128, NMS_SMEM>>>();
    topk_kernel<<<BATCH, 1024, TOPK_SMEM>>>(out, out_size);
}

// round 9
// speedup vs baseline: 1.0506x; 1.0506x over previous
#include <cuda_runtime.h>
#include <cuda_bf16.h>
#include <math.h>

// Problem constants (match reference)
#define BATCH     8
#define NPI       1000      // proposals per image
#define NC        81        // classes incl. background
#define CF        80        // foreground classes
#define BN        (BATCH*NPI)
#define DETS      100
#define SCORE_TH  0.05f
#define NMS_TH    0.5f
#define IMG_W1    1332.0f   // IMG_W - 1
#define IMG_H1    799.0f    // IMG_H - 1
#define DW_CLIP_F 4.135166556742356f   // log(1000/16)

#define CAND_CAP  (CF * DETS)   // 8000: per-class cap 100 makes this exact

typedef unsigned long long u64;
typedef unsigned int u32;

// Scratch (device globals; no allocation allowed)
__device__ float g_scores[BATCH * CF * NPI];        // [b][c0][n]   (NMS reads coalesced)
__device__ float g_boxes [BN * CF * 4];             // [n_global][c0][4] (coalesced writes)
__device__ u64   g_cand[BATCH * CAND_CAP];          // per-image kept entries
__device__ int   g_cnt[BATCH];

// ===========================================================================
// Warp-register bitonic machinery: 128 u64 keys per warp, 4 per lane,
// element index e = r*32 + lane. Descending order. No barriers, no smem.
// ===========================================================================
__device__ __forceinline__ void cedir(u64 &a, u64 &b, bool maxlow) {
    u64 mx = a > b ? a : b;
    u64 mn = a > b ? b : a;
    a = maxlow ? mx : mn;
    b = maxlow ? mn : mx;
}

__device__ __forceinline__ void shflpass(u64 v[4], int lane, int k, int j) {
    #pragma unroll
    for (int r = 0; r < 4; r++) {
        u64 o = __shfl_xor_sync(0xFFFFFFFFu, v[r], j);
        int e = (r << 5) | lane;
        bool keepmax = (((e & k) == 0) == ((lane & j) == 0));
        bool gt = v[r] > o;
        u64 mx = gt ? v[r] : o;
        u64 mn = gt ? o : v[r];
        v[r] = keepmax ? mx : mn;
    }
}

__device__ __forceinline__ void warp_sort128_desc(u64 v[4], int lane) {
    #pragma unroll
    for (int k = 2; k <= 32; k <<= 1) {
        #pragma unroll
        for (int j = k >> 1; j >= 1; j >>= 1) shflpass(v, lane, k, j);
    }
    // k = 64: j=32 is a register exchange (pairs (v0,v1) desc, (v2,v3) asc)
    cedir(v[0], v[1], true);
    cedir(v[2], v[3], false);
    #pragma unroll
    for (int j = 16; j >= 1; j >>= 1) shflpass(v, lane, 64, j);
    // k = 128: j=64, j=32 register exchanges, all-descending
    cedir(v[0], v[2], true); cedir(v[1], v[3], true);
    cedir(v[0], v[1], true); cedir(v[2], v[3], true);
    #pragma unroll
    for (int j = 16; j >= 1; j >>= 1) shflpass(v, lane, 128, j);
}

// Clean a bitonic 128-sequence into descending order.
__device__ __forceinline__ void warp_merge128_desc(u64 v[4], int lane) {
    cedir(v[0], v[2], true); cedir(v[1], v[3], true);
    cedir(v[0], v[1], true); cedir(v[2], v[3], true);
    #pragma unroll
    for (int j = 16; j >= 1; j >>= 1) {
        #pragma unroll
        for (int r = 0; r < 4; r++) {
            u64 o = __shfl_xor_sync(0xFFFFFFFFu, v[r], j);
            bool keepmax = ((lane & j) == 0);
            bool gt = v[r] > o;
            u64 mx = gt ? v[r] : o;
            u64 mn = gt ? o : v[r];
            v[r] = keepmax ? mx : mn;
        }
    }
}

// ===========================================================================
// One WARP per proposal: shfl softmax over 81 classes, decode+clip 80 boxes.
// Boxes stored [n_global][c0][4] -> coalesced float4 stores.
// ===========================================================================
__global__ void softmax_decode_kernel(const float* __restrict__ logits,
                                      const float* __restrict__ reg,
                                      const float* __restrict__ props) {
    if (blockIdx.x == 0 && threadIdx.x < BATCH) g_cnt[threadIdx.x] = 0;

    int n    = (blockIdx.x * blockDim.x + threadIdx.x) >> 5;
    int lane = threadIdx.x & 31;
    if (n >= BN) return;

    const float* lrow = logits + n * NC;
    float l0 = lrow[lane];
    float l1 = lrow[lane + 32];
    float l2 = (lane + 64 < NC) ? lrow[lane + 64] : -INFINITY;

    float mx = fmaxf(l0, fmaxf(l1, l2));
    #pragma unroll
    for (int o = 16; o > 0; o >>= 1) mx = fmaxf(mx, __shfl_xor_sync(0xFFFFFFFFu, mx, o));

    float e0 = expf(l0 - mx);
    float e1 = expf(l1 - mx);
    float e2 = (lane + 64 < NC) ? expf(l2 - mx) : 0.0f;
    float sm = e0 + e1 + e2;
    #pragma unroll
    for (int o = 16; o > 0; o >>= 1) sm += __shfl_xor_sync(0xFFFFFFFFu, sm, o);
    float inv = 1.0f / sm;

    float4 p = *(const float4*)(props + n * 4);
    float w  = p.z - p.x + 1.0f;
    float h  = p.w - p.y + 1.0f;
    float cx = p.x + 0.5f * w;
    float cy = p.y + 0.5f * h;

    int b  = n / NPI;
    int nl = n - b * NPI;

    #pragma unroll
    for (int s = 0; s < 3; s++) {
        int c = lane + 32 * s;
        if (c >= 1 && c < NC) {
            int c0 = c - 1;
            float e = (s == 0) ? e0 : (s == 1) ? e1 : e2;
            g_scores[(b * CF + c0) * NPI + nl] = e * inv;

            float4 r = *(const float4*)(reg + n * (NC * 4) + c * 4);
            float dx = r.x * 0.1f;
            float dy = r.y * 0.1f;
            float dw = fminf(r.z * 0.2f, DW_CLIP_F);
            float dh = fminf(r.w * 0.2f, DW_CLIP_F);

            float pcx = dx * w + cx;
            float pcy = dy * h + cy;
            float pw  = expf(dw) * w;
            float ph  = expf(dh) * h;

            float bx0 = fminf(fmaxf(pcx - 0.5f * pw, 0.0f), IMG_W1);
            float by0 = fminf(fmaxf(pcy - 0.5f * ph, 0.0f), IMG_H1);
            float bx1 = fminf(fmaxf(pcx + 0.5f * pw - 1.0f, 0.0f), IMG_W1);
            float by1 = fminf(fmaxf(pcy + 0.5f * ph - 1.0f, 0.0f), IMG_H1);

            // coalesced: consecutive c0 across lanes
            *(float4*)(g_boxes + ((size_t)n * CF + c0) * 4) =
                make_float4(bx0, by0, bx1, by1);
        }
    }
}

// ===========================================================================
// One block (128 thr) per (image,class): compact, warp-register sort,
// pairwise-suppression bitmask, single-thread barrier-free greedy scan.
// Dynamic smem layout:
//   [0,8192)       u64   skey[1024]
//   [8192,24576)   float4 sbox[1024]
//   [24576,28672)  float sarea[1024]
//   [28672,36864)  u32   smask[256*8]   (or uchar ssup[1024] overlay, fallback)
//   [36864,37696)  u64   skept[104]
// ===========================================================================
#define NMS_SMEM 37696

__global__ void nms_kernel() {
    extern __shared__ char nsm[];
    u64*    skey  = (u64*)nsm;
    float4* sbox  = (float4*)(nsm + 8192);
    float*  sarea = (float*)(nsm + 24576);
    u32*    smask = (u32*)(nsm + 28672);
    unsigned char* ssup = (unsigned char*)(nsm + 28672);
    u64*    skept = (u64*)(nsm + 36864);

    __shared__ int s_cnt, s_kcnt, s_base;

    int task = blockIdx.x;       // 0..639
    int b  = task / CF;
    int c0 = task - b * CF;
    int tid  = threadIdx.x;      // 0..127
    int lane = tid & 31;
    int wrp  = tid >> 5;

    if (tid == 0) s_cnt = 0;
    __syncthreads();

    // --- compact valid scores ---
    const float* sc_base = g_scores + (b * CF + c0) * NPI;
    for (int i = tid; i < NPI; i += 128) {
        float s = sc_base[i];
        if (s > SCORE_TH) {
            int p = atomicAdd(&s_cnt, 1);
            skey[p] = ((u64)__float_as_uint(s) << 32) | (u64)(0xFFFFFFFFu - (u32)i);
        }
    }
    __syncthreads();
    int m = s_cnt;
    if (m == 0) return;

    // --- sort descending (score, then lower proposal index) ---
    if (m <= 128) {
        if (wrp == 0) {
            u64 v[4];
            #pragma unroll
            for (int r = 0; r < 4; r++) {
                int e = r * 32 + lane;
                v[r] = (e < m) ? skey[e] : 0ull;
            }
            warp_sort128_desc(v, lane);
            #pragma unroll
            for (int r = 0; r < 4; r++) skey[r * 32 + lane] = v[r];
        }
        __syncthreads();
    } else {
        int L = 128;
        while (L < m) L <<= 1;
        for (int i = m + tid; i < L; i += 128) skey[i] = 0ull;
        __syncthreads();
        for (int k = 2; k <= L; k <<= 1) {
            for (int j = k >> 1; j > 0; j >>= 1) {
                for (int i = tid; i < L; i += 128) {
                    int ixj = i ^ j;
                    if (ixj > i) {
                        u64 a = skey[i], c = skey[ixj];
                        if (((i & k) == 0) ? (a < c) : (a > c)) {
                            skey[i] = c; skey[ixj] = a;
                        }
                    }
                }
                __syncthreads();
            }
        }
    }

    // --- gather boxes in sorted order ---
    for (int i = tid; i < m; i += 128) {
        u32 n = 0xFFFFFFFFu - (u32)(skey[i] & 0xFFFFFFFFull);
        int ng = b * NPI + (int)n;
        float4 bx = *(const float4*)(g_boxes + ((size_t)ng * CF + c0) * 4);
        sbox[i] = bx;
        sarea[i] = (bx.z - bx.x) * (bx.w - bx.y);   // torchvision IoU (no +1)
    }
    __syncthreads();

    u64 keysub = (u64)((u32)c0 * NPI);   // skey -> image-flat key conversion

    if (m <= 256) {
        // --- pairwise suppression bit-matrix (stride 8 u32 words per row) ---
        for (int idx = tid; idx < m * 8; idx += 128) smask[idx] = 0;
        __syncthreads();
        for (int idx = tid; idx < m * m; idx += 128) {
            int i = idx / m;
            int j = idx - i * m;
            if (j > i) {
                float4 bi = sbox[i], bj = sbox[j];
                float lx = fmaxf(bi.x, bj.x);
                float ly = fmaxf(bi.y, bj.y);
                float rx = fminf(bi.z, bj.z);
                float ry = fminf(bi.w, bj.w);
                float iw = fmaxf(rx - lx, 0.0f);
                float ih = fmaxf(ry - ly, 0.0f);
                float inter = iw * ih;
                float iou = inter / (sarea[i] + sarea[j] - inter + 1e-9f);
                if (iou > NMS_TH)
                    atomicOr(&smask[i * 8 + (j >> 5)], 1u << (j & 31));
            }
        }
        __syncthreads();

        // --- barrier-free greedy scan (single thread, pure bit ops) ---
        if (tid == 0) {
            u32 rem[8] = {0,0,0,0,0,0,0,0};
            int kc = 0;
            for (int i = 0; i < m; i++) {
                if (!((rem[i >> 5] >> (i & 31)) & 1u)) {
                    skept[kc++] = skey[i] - keysub;
                    if (kc == DETS) break;
                    #pragma unroll
                    for (int w2 = 0; w2 < 8; w2++) rem[w2] |= smask[i * 8 + w2];
                }
            }
            s_kcnt = kc;
            s_base = atomicAdd(&g_cnt[b], kc);
        }
        __syncthreads();
        if (tid < s_kcnt) g_cand[b * CAND_CAP + s_base + tid] = skept[tid];
    } else {
        // --- fallback: barrier greedy (m > 256; never hit on this data) ---
        for (int i = tid; i < m; i += 128) ssup[i] = 0;
        if (tid == 0) s_kcnt = 0;
        __syncthreads();
        for (int i = 0; i < m; i++) {
            if (!ssup[i]) {
                if (tid == 0 && s_kcnt < DETS) {
                    skept[s_kcnt++] = skey[i] - keysub;
                }
                float4 bi = sbox[i];
                float ai = sarea[i];
                for (int j = i + 1 + tid; j < m; j += 128) {
                    if (!ssup[j]) {
                        float4 bj = sbox[j];
                        float lx = fmaxf(bi.x, bj.x);
                        float ly = fmaxf(bi.y, bj.y);
                        float rx = fminf(bi.z, bj.z);
                        float ry = fminf(bi.w, bj.w);
                        float iw = fmaxf(rx - lx, 0.0f);
                        float ih = fmaxf(ry - ly, 0.0f);
                        float inter = iw * ih;
                        float iou = inter / (ai + sarea[j] - inter + 1e-9f);
                        if (iou > NMS_TH) ssup[j] = 1;
                    }
                }
            }
            __syncthreads();
        }
        if (tid == 0) s_base = atomicAdd(&g_cnt[b], s_kcnt);
        __syncthreads();
        if (tid < s_kcnt) g_cand[b * CAND_CAP + s_base + tid] = skept[tid];
    }
}

// ===========================================================================
// One block (1024 thr = 32 warps) per image. Warp-register bitonic top-k:
// each warp reduces its 256-chunk to a sorted top-128, then 5 tree merge
// rounds (one barrier each). Warp 0 emits the top-100.
// smem: bufA 32*128 u64 (32KB) + bufB 16*128 u64 (16KB) = 48KB dynamic.
// ===========================================================================
#define TOPK_SMEM (48 * 1024)

__global__ void topk_kernel(float* __restrict__ out, int out_size) {
    extern __shared__ u64 tsm[];
    u64* A  = tsm;            // 32 lists of 128
    u64* Bf = tsm + 32 * 128; // 16 lists of 128

    int b    = blockIdx.x;
    int tid  = threadIdx.x;
    int lane = tid & 31;
    int w    = tid >> 5;
    int M    = g_cnt[b];
    if (M > CAND_CAP) M = CAND_CAP;
    const u64* cand = g_cand + b * CAND_CAP;

    // per-warp: load 256, sort two 128s, keep top-128
    u64 v[4], u[4];
    int base = w * 256;
    #pragma unroll
    for (int r = 0; r < 4; r++) {
        int e = base + r * 32 + lane;
        v[r] = (e < M) ? cand[e] : 0ull;
        int e2 = e + 128;
        u[r] = (e2 < M) ? cand[e2] : 0ull;
    }
    warp_sort128_desc(v, lane);
    warp_sort128_desc(u, lane);
    {   // top-128 of the two sorted lists: v[e] = max(v[e], u[127-e])
        u64 o0 = __shfl_xor_sync(0xFFFFFFFFu, u[3], 31);
        u64 o1 = __shfl_xor_sync(0xFFFFFFFFu, u[2], 31);
        u64 o2 = __shfl_xor_sync(0xFFFFFFFFu, u[1], 31);
        u64 o3 = __shfl_xor_sync(0xFFFFFFFFu, u[0], 31);
        v[0] = v[0] > o0 ? v[0] : o0;
        v[1] = v[1] > o1 ? v[1] : o1;
        v[2] = v[2] > o2 ? v[2] : o2;
        v[3] = v[3] > o3 ? v[3] : o3;
        warp_merge128_desc(v, lane);
    }
    #pragma unroll
    for (int r = 0; r < 4; r++) A[w * 128 + r * 32 + lane] = v[r];
    __syncthreads();

    // tree merge rounds: 32 -> 16 -> 8 -> 4 -> 2 -> 1 lists
    #pragma unroll
    for (int round = 0; round < 5; round++) {
        int nl = 16 >> round;                       // active warps this round
        const u64* src = (round & 1) ? Bf : A;
        u64*       dst = (round & 1) ? A  : Bf;
        if (w < nl) {
            const u64* pa = src + (2 * w) * 128;
            const u64* pb = src + (2 * w + 1) * 128;
            #pragma unroll
            for (int r = 0; r < 4; r++) {
                int e = r * 32 + lane;
                u64 a  = pa[e];
                u64 bb = pb[127 - e];
                v[r] = a > bb ? a : bb;
            }
            warp_merge128_desc(v, lane);
            if (nl > 1) {
                #pragma unroll
                for (int r = 0; r < 4; r++) dst[w * 128 + r * 32 + lane] = v[r];
            }
        }
        __syncthreads();
    }

    // warp 0 holds the final sorted 128 in v -> emit top 100
    bool write_labels = (out_size >= BATCH * DETS * 5 + BATCH * DETS);
    if (w == 0) {
        #pragma unroll
        for (int r = 0; r < 4; r++) {
            int e = r * 32 + lane;
            if (e < DETS) {
                u64 bk = v[r];
                float* drow = out + (b * DETS + e) * 5;
                if (bk == 0) {
                    drow[0] = 0.0f; drow[1] = 0.0f; drow[2] = 0.0f;
                    drow[3] = 0.0f; drow[4] = 0.0f;
                    if (write_labels)
                        out[BATCH * DETS * 5 + b * DETS + e] = -1.0f;
                } else {
                    float sc = __uint_as_float((u32)(bk >> 32));
                    u32 flat = 0xFFFFFFFFu - (u32)(bk & 0xFFFFFFFFull);
                    int c0 = (int)(flat / NPI);
                    int n  = (int)(flat - (u32)c0 * NPI);
                    int ng = b * NPI + n;
                    const float* bx = g_boxes + ((size_t)ng * CF + c0) * 4;
                    drow[0] = bx[0]; drow[1] = bx[1];
                    drow[2] = bx[2]; drow[3] = bx[3];
                    drow[4] = sc;
                    if (write_labels)
                        out[BATCH * DETS * 5 + b * DETS + e] = (float)(c0 + 1);
                }
            }
        }
    }
}

// ---------------------------------------------------------------------------
extern "C" void kernel_launch(void* const* d_in, const int* in_sizes, int n_in,
                              void* d_out, int out_size) {
    const float* class_logits   = (const float*)d_in[0];  // [8000, 81]
    const float* box_regression = (const float*)d_in[1];  // [8000, 324]
    const float* proposals      = (const float*)d_in[2];  // [8000, 4]
    // d_in[3] = features (unused)

    float* out = (float*)d_out;

    cudaFuncSetAttribute(topk_kernel,
                         cudaFuncAttributeMaxDynamicSharedMemorySize, TOPK_SMEM);
    cudaFuncSetAttribute(nms_kernel,
                         cudaFuncAttributeMaxDynamicSharedMemorySize, NMS_SMEM);

    softmax_decode_kernel<<<BN / 8, 256>>>(class_logits, box_regression, proposals);
    nms_kernel<<<BATCH * CF, 128, NMS_SMEM>>>();
    topk_kernel<<<BATCH, 1024, TOPK_SMEM>>>(out, out_size);
}